// round 12
// baseline (speedup 1.0000x reference)
#include <cuda_runtime.h>
#include <cstdint>
#include <float.h>
#include <math.h>

// Problem constants (fixed by the dataset)
#define TT 64
#define UU 142
#define II 4500
#define BB 16384
#define KK 10

#define NPER 5                 // lane-major: lane owns users v = 5*lane + j
#define FULL_MASK 0xFFFFFFFFu

// Candidate threshold: sims are 0.5(s+s^T) ~ triangular(-1,1).
// P(sim > 0.35) ~ 0.21 -> E[|C|] ~ 30, E[rated in C] ~ 21.
// P(<10 rated candidates) small -> exact full fallback.
#define THETA 0.35f

// order-preserving float->uint map (monotone increasing); 0 reserved as
// "invalid/consumed" sentinel (all real keys >= f2ord(0.0) = 0x80000000 > 0)
__device__ __forceinline__ unsigned f2ord(float f) {
    unsigned b = __float_as_uint(f);
    return (b & 0x80000000u) ? ~b : (b | 0x80000000u);
}
// exact inverse of f2ord
__device__ __forceinline__ float ord2f(unsigned o) {
    return __uint_as_float((o & 0x80000000u) ? (o ^ 0x80000000u) : ~o);
}

__global__ __launch_bounds__(128)
void ucf_kernel(const float* __restrict__ qos,      // (T,U,I)
                const float* __restrict__ uavg,     // (T,U)
                const float* __restrict__ sim,      // (U,U)
                const int*   __restrict__ user_id,  // (B,)
                const int*   __restrict__ item_id,  // (B,)
                const int*   __restrict__ time_id,  // (B,)
                float*       __restrict__ out)      // (B,)
{
    const int warp = (blockIdx.x * blockDim.x + threadIdx.x) >> 5;
    const int lane = threadIdx.x & 31;
    if (warp >= BB) return;

    const int u = __ldg(user_id + warp);
    const int i = __ldg(item_id + warp);
    const int t = __ldg(time_id + warp);

    const float* __restrict__ qbase = qos + (size_t)t * (UU * II) + i;
    const float* __restrict__ srow  = sim + (size_t)u * UU;
    const float* __restrict__ arow  = uavg + (size_t)t * UU;

    const int vbase = lane * NPER;   // lane-major: v = 5*lane + j

    // 1) sim row (L2-resident; 5 consecutive floats per lane)
    float sv[NPER];
    #pragma unroll
    for (int j = 0; j < NPER; j++) {
        const int v = vbase + j;
        sv[j] = (v < UU) ? __ldg(srow + v) : 0.0f;
    }

    // 2) candidates: sim > THETA; probe qos ONLY for candidates
    unsigned candmask = 0;
    #pragma unroll
    for (int j = 0; j < NPER; j++) {
        const int v = vbase + j;
        if (v < UU && sv[j] > THETA) candmask |= 1u << j;
    }

    float qv[NPER];
    #pragma unroll
    for (int j = 0; j < NPER; j++) {
        const int v = vbase + j;
        qv[j] = ((candmask >> j) & 1u) ? __ldg(qbase + (size_t)v * II) : 0.0f;
    }

    // 3) count rated candidates: per-lane popc + one warp add-reduce
    unsigned ratedmask = 0;
    #pragma unroll
    for (int j = 0; j < NPER; j++)
        if (((candmask >> j) & 1u) && qv[j] > 0.0f) ratedmask |= 1u << j;
    const int cnt = __reduce_add_sync(FULL_MASK, __popc(ratedmask));

    // 4) keys: fast path if top-10 provably among rated candidates
    unsigned ordu[NPER];
    if (cnt >= KK) {
        // Non-candidates are unrated (masked 0 < THETA) or rated with
        // sim <= THETA < candidate sims -> cannot displace rated candidates.
        #pragma unroll
        for (int j = 0; j < NPER; j++)
            ordu[j] = ((ratedmask >> j) & 1u) ? f2ord(sv[j]) : 0u;
    } else {
        // Rare exact fallback: full masked top-K semantics over all 142
        #pragma unroll
        for (int j = 0; j < NPER; j++) {
            const int v = vbase + j;
            qv[j] = (v < UU) ? __ldg(qbase + (size_t)v * II) : 0.0f;
        }
        #pragma unroll
        for (int j = 0; j < NPER; j++) {
            const int v = vbase + j;
            const bool ok = (v < UU);
            const float m = (ok && qv[j] > 0.0f) ? sv[j] : 0.0f;
            ordu[j] = ok ? f2ord(m) : 0u;
        }
    }

    // 5) top-K: key-zeroing scan + single REDUX.MAX + ballot/ffs tie-break.
    //    Lane-major ownership => lowest lane (after strict-'>' ascending-j
    //    local scan) == lowest global index: exact jax.lax.top_k semantics.
    unsigned selmask = 0;
    float S = 0.0f;                                // uniform across lanes
    #pragma unroll
    for (int k = 0; k < KK; k++) {
        unsigned bestord = 0u;
        int bestj = 0;
        #pragma unroll
        for (int j = 0; j < NPER; j++)
            if (ordu[j] > bestord) { bestord = ordu[j]; bestj = j; }

        const unsigned maxord  = __reduce_max_sync(FULL_MASK, bestord);
        const unsigned winners = __ballot_sync(FULL_MASK, bestord == maxord);
        S += ord2f(maxord);                        // k-th largest, all lanes
        if (lane == __ffs(winners) - 1) {
            #pragma unroll
            for (int j = 0; j < NPER; j++) {
                if (j == bestj) {
                    ordu[j] = 0u;                  // consume
                    selmask |= 1u << j;
                }
            }
        }
    }

    const float denom = S + 1e-8f;

    // 6) epilogue: sum_k w_k * (r_k - avg_k), per-element nan_to_num(w)
    float acc = 0.0f;
    #pragma unroll
    for (int j = 0; j < NPER; j++) {
        if ((selmask >> j) & 1u) {
            const int v = vbase + j;
            // selected weight: fast path -> sv[j]; fallback -> masked value,
            // which equals sv[j] when rated else 0; recompute mask cheaply:
            float s = (qv[j] > 0.0f) ? sv[j] : 0.0f;
            float w = s / denom;
            if (isnan(w))      w = 0.0f;
            else if (isinf(w)) w = copysignf(3.4028234663852886e38f, w);
            acc += w * (qv[j] - __ldg(arow + v));
        }
    }
    #pragma unroll
    for (int off = 16; off > 0; off >>= 1)
        acc += __shfl_xor_sync(FULL_MASK, acc, off);

    if (lane == 0)
        out[warp] = __ldg(arow + u) + acc;
}

extern "C" void kernel_launch(void* const* d_in, const int* in_sizes, int n_in,
                              void* d_out, int out_size)
{
    const float* qos   = (const float*)d_in[0];  // (64,142,4500)
    const float* uavg  = (const float*)d_in[1];  // (64,142)
    const float* sim   = (const float*)d_in[2];  // (142,142)
    const int*   uid   = (const int*)  d_in[3];  // (16384,)
    const int*   iid   = (const int*)  d_in[4];  // (16384,)
    const int*   tid   = (const int*)  d_in[5];  // (16384,)
    float*       out   = (float*)d_out;          // (16384,)

    const int threads = 128;                 // 4 warps/block: finer wave tail
    const int blocks  = (BB * 32) / threads; // 4096
    ucf_kernel<<<blocks, threads>>>(qos, uavg, sim, uid, iid, tid, out);
}